// round 16
// baseline (speedup 1.0000x reference)
#include <cuda_runtime.h>
#include <cuda_fp16.h>
#include <cstdint>

#define NUM_NODES 100000
#define HID 64
#define WTILES_PER_HALF (NUM_NODES / 16)      // 6250 warp-tiles per table
#define WTILES_TOTAL (2 * WTILES_PER_HALF)    // 12500
#define PRE_BLOCKS 740                        // 148 SMs x 5 resident: 1 wave
#define EDGE_BLOCKS 1184                      // 148 SMs x 8 CTAs: single wave

// Scratch tables in fp16 (allocation-free rule: __device__ globals).
__device__ __half g_U[NUM_NODES * HID];
__device__ __half g_B[NUM_NODES * HID];

__device__ __forceinline__ uint32_t f2h2(float x, float y) {
    __half2 h = __floats2half2_rn(x, y);
    return *reinterpret_cast<uint32_t*>(&h);
}
__device__ __forceinline__ void mma_f16(float* c, uint32_t a0, uint32_t a1,
                                        uint32_t a2, uint32_t a3,
                                        uint32_t b0, uint32_t b1) {
    asm volatile(
        "mma.sync.aligned.m16n8k16.row.col.f32.f16.f16.f32 "
        "{%0,%1,%2,%3}, {%4,%5,%6,%7}, {%8,%9}, {%0,%1,%2,%3};"
        : "+f"(c[0]), "+f"(c[1]), "+f"(c[2]), "+f"(c[3])
        : "r"(a0), "r"(a1), "r"(a2), "r"(a3), "r"(b0), "r"(b1));
}

// ---------------------------------------------------------------------------
// Phase 1: single-pass fp16 HMMA GEMM (fp32 accumulate, fp16 store).
//
// Output-column permutation: actual col j sits in MMA jt=(j&15)>>1 at
// fragment slot f=2*(j>>4)+(j&1) -> lane tc owns contiguous half2 cols
// 8tc..8tc+7 -> 4 coalesced STG.128 epilogue.
// K-axis permutation: lane tc's A fragments per K16-step are the contiguous
// physical k-pairs (8ks+2tc, 8ks+2tc+1) -> ONE float4 load per row per step.
//
// One warp-tile = 16 nodes x 64 outputs, K=64 -> 8 jt x 4 ks = 32 MMAs.
// Tiles [0,6250) -> U (+b1), rest -> B.
// Residency: 5 CTAs/SM (launch_bounds caps regs at 51), 740 blocks = one
// resident wave, 40 warps/SM for DRAM-latency hiding (kernel is
// latency-bound per the R13->R14 residency experiment).
// ---------------------------------------------------------------------------
__global__ void __launch_bounds__(256, 5) precompute_mma(
    const float* __restrict__ z_user,
    const float* __restrict__ z_books,
    const float* __restrict__ W1,    // [64][128]
    const float* __restrict__ b1)    // [64]
{
    __shared__ uint32_t Wq[4096];    // 16 KB fragment-layout W
    __shared__ float b1s[64];

    int tid = threadIdx.x;
    #pragma unroll
    for (int it = 0; it < 16; it++) {
        int i = it * 256 + tid;          // linear element 0..4095
        int half = i >> 11;              // 0 = user cols, 1 = book cols
        int j    = (i >> 5) & 63;
        int k2   = i & 31;               // physical k-pair index
        float2 w = *(const float2*)(W1 + j * 128 + half * 64 + k2 * 2);
        int jt = (j & 15) >> 1;          // permuted MMA index
        int f  = 2 * (j >> 4) + (j & 1); // fragment n-slot
        int ks = k2 >> 3, t = k2 & 7;
        int tc = t >> 1, sel = t & 1;    // K-permuted: pair (8ks+2tc+sel)
        int entry = (((half * 8 + jt) * 4 + ks) * 8 + f) * 4 + tc;
        Wq[entry * 2 + sel] = f2h2(w.x, w.y);
    }
    if (tid < 64) b1s[tid] = b1[tid];
    __syncthreads();

    int wid = tid >> 5, lane = tid & 31;
    int g = lane >> 2, tc = lane & 3;

    for (int wt = blockIdx.x * 8 + wid; wt < WTILES_TOTAL; wt += PRE_BLOCKS * 8) {
        bool isU = (wt < WTILES_PER_HALF);
        int tile = isU ? wt : wt - WTILES_PER_HALF;
        int nb = tile * 16;
        const float* z = isU ? z_user : z_books;
        int half = isU ? 0 : 1;

        const float4* zr0 = (const float4*)(z + (size_t)(nb + g) * HID);
        const float4* zr1 = (const float4*)(z + (size_t)(nb + g + 8) * HID);

        float acc[8][4];
        #pragma unroll
        for (int jt = 0; jt < 8; jt++)
            #pragma unroll
            for (int c = 0; c < 4; c++) acc[jt][c] = 0.f;

        #pragma unroll
        for (int ks = 0; ks < 4; ks++) {
            // A fragments: one float4 per row covers both k-pairs for lane tc
            float4 q0 = zr0[ks * 4 + tc];
            float4 q1 = zr1[ks * 4 + tc];
            uint32_t a0 = f2h2(q0.x, q0.y);   // pair 8ks+2tc   , row g
            uint32_t a2 = f2h2(q0.z, q0.w);   // pair 8ks+2tc+1 , row g
            uint32_t a1 = f2h2(q1.x, q1.y);   // pair 8ks+2tc   , row g+8
            uint32_t a3 = f2h2(q1.z, q1.w);   // pair 8ks+2tc+1 , row g+8

            #pragma unroll
            for (int jt = 0; jt < 8; jt++) {
                int entry = (((half * 8 + jt) * 4 + ks) * 8 + g) * 4 + tc;
                uint2 b = *(const uint2*)(Wq + entry * 2);  // conflict-free LDS.64
                mma_f16(acc[jt], a0, a1, a2, a3, b.x, b.y);
            }
        }

        // Epilogue: lane (g,tc) owns rows g/g+8, half2 cols 8tc+jt (jt=0..7).
        __half* table = isU ? g_U : g_B;
        uint4* p0 = (uint4*)(table + (size_t)(nb + g) * HID + tc * 16);
        uint4* p1 = (uint4*)(table + (size_t)(nb + g + 8) * HID + tc * 16);
        #pragma unroll
        for (int hb = 0; hb < 2; hb++) {     // two 16B store chunks per row
            uint32_t h0[4], h1[4];
            #pragma unroll
            for (int v = 0; v < 4; v++) {
                int jt = hb * 4 + v;
                int c0 = 16 * tc + 2 * jt;   // actual output column
                float bx = 0.f, by = 0.f;
                if (isU) { bx = b1s[c0]; by = b1s[c0 + 1]; }
                h0[v] = f2h2(acc[jt][0] + bx, acc[jt][1] + by);
                h1[v] = f2h2(acc[jt][2] + bx, acc[jt][3] + by);
            }
            p0[hb] = make_uint4(h0[0], h0[1], h0[2], h0[3]);
            p1[hb] = make_uint4(h1[0], h1[1], h1[2], h1[3]);
        }
    }
}

// ---------------------------------------------------------------------------
// Phase 2: per-edge decode on fp16 tables — at the ~13 TB/s LTS roofline.
// Single resident wave (1184 CTAs), 8 lanes/edge, two edge slots per trip,
// half2 math, fp32 shuffle reduce. launch_bounds(256,8) pins 32 regs.
// ---------------------------------------------------------------------------
__global__ void __launch_bounds__(256, 8) edge_kernel(
    const int* __restrict__ idx,         // [2][E] int32
    const float* __restrict__ W2,        // [1][64]
    const float* __restrict__ b2,        // [1]
    float* __restrict__ out,             // [E]
    int E)
{
    int lane = threadIdx.x & 31;
    int q  = lane >> 3;                  // edge slot within warp-pass (0..3)
    int l8 = lane & 7;                   // feature chunk: 8 halves per lane

    float4 w0 = ((const float4*)W2)[2 * l8];
    float4 w1 = ((const float4*)W2)[2 * l8 + 1];
    __half2 wh0 = __floats2half2_rn(w0.x, w0.y);
    __half2 wh1 = __floats2half2_rn(w0.z, w0.w);
    __half2 wh2 = __floats2half2_rn(w1.x, w1.y);
    __half2 wh3 = __floats2half2_rn(w1.z, w1.w);
    float  b2v = b2[0];

    int gw = (blockIdx.x * blockDim.x + threadIdx.x) >> 5;
    int warps = (gridDim.x * blockDim.x) >> 5;

    const __half2 zero2 = __float2half2_rn(0.f);

    for (int e0 = gw * 8; e0 < E; e0 += warps * 8) {
        int eA = e0 + q;
        int eB = e0 + 4 + q;
        bool vA = (eA < E);
        bool vB = (eB < E);

        int rA = vA ? idx[eA]     : 0;
        int cA = vA ? idx[E + eA] : 0;
        int rB = vB ? idx[eB]     : 0;
        int cB = vB ? idx[E + eB] : 0;

        // 4 independent 16B gathers per thread
        uint4 uA = *(const uint4*)(g_U + (size_t)rA * HID + l8 * 8);
        uint4 bA = *(const uint4*)(g_B + (size_t)cA * HID + l8 * 8);
        uint4 uB = *(const uint4*)(g_U + (size_t)rB * HID + l8 * 8);
        uint4 bB = *(const uint4*)(g_B + (size_t)cB * HID + l8 * 8);

        float pA, pB;
        {
            const __half2* u = (const __half2*)&uA;
            const __half2* b = (const __half2*)&bA;
            __half2 h0 = __hmax2(__hadd2(u[0], b[0]), zero2);
            __half2 h1 = __hmax2(__hadd2(u[1], b[1]), zero2);
            __half2 h2 = __hmax2(__hadd2(u[2], b[2]), zero2);
            __half2 h3 = __hmax2(__hadd2(u[3], b[3]), zero2);
            __half2 a = __hmul2(h0, wh0);
            a = __hfma2(h1, wh1, a);
            a = __hfma2(h2, wh2, a);
            a = __hfma2(h3, wh3, a);
            float2 f = __half22float2(a);
            pA = f.x + f.y;
        }
        {
            const __half2* u = (const __half2*)&uB;
            const __half2* b = (const __half2*)&bB;
            __half2 h0 = __hmax2(__hadd2(u[0], b[0]), zero2);
            __half2 h1 = __hmax2(__hadd2(u[1], b[1]), zero2);
            __half2 h2 = __hmax2(__hadd2(u[2], b[2]), zero2);
            __half2 h3 = __hmax2(__hadd2(u[3], b[3]), zero2);
            __half2 a = __hmul2(h0, wh0);
            a = __hfma2(h1, wh1, a);
            a = __hfma2(h2, wh2, a);
            a = __hfma2(h3, wh3, a);
            float2 f = __half22float2(a);
            pB = f.x + f.y;
        }

        pA += __shfl_xor_sync(0xffffffffu, pA, 1);
        pB += __shfl_xor_sync(0xffffffffu, pB, 1);
        pA += __shfl_xor_sync(0xffffffffu, pA, 2);
        pB += __shfl_xor_sync(0xffffffffu, pB, 2);
        pA += __shfl_xor_sync(0xffffffffu, pA, 4);
        pB += __shfl_xor_sync(0xffffffffu, pB, 4);

        if (l8 == 0) {
            if (vA) out[eA] = pA + b2v;
            if (vB) out[eB] = pB + b2v;
        }
    }
}

// ---------------------------------------------------------------------------
extern "C" void kernel_launch(void* const* d_in, const int* in_sizes, int n_in,
                              void* d_out, int out_size)
{
    const float* z_user  = (const float*)d_in[0];
    const float* z_books = (const float*)d_in[1];
    const int*   idx     = (const int*)d_in[2];
    const float* W1      = (const float*)d_in[3];
    const float* b1      = (const float*)d_in[4];
    const float* W2      = (const float*)d_in[5];
    const float* b2      = (const float*)d_in[6];
    float*       out     = (float*)d_out;

    int E = in_sizes[2] / 2;             // edge_label_index is [2, E]

    // Phase 1: single resident wave (5 CTAs/SM), ~2 warp-tiles per warp
    precompute_mma<<<PRE_BLOCKS, 256>>>(z_user, z_books, W1, b1);

    // Phase 2: single resident wave, 9472 warps * 8 edges per trip
    edge_kernel<<<EDGE_BLOCKS, 256>>>(idx, W2, b2, out, E);
}